// round 10
// baseline (speedup 1.0000x reference)
#include <cuda_runtime.h>
#include <cuda_fp16.h>
#include <math.h>
#include <stdint.h>

// Problem constants
#define T_STEPS  256
#define BATCH    64
#define VOCAB    32000
#define D_EMBED  512
#define D_HIDDEN 1024
#define G4       (4 * D_HIDDEN)          // 4096
#define NH       (BATCH * D_HIDDEN)      // 65536
#define NCTA     128
#define NGROUP   8
#define GSIZE    16

// Scratch
__device__ float    g_xgates[(size_t)T_STEPS * BATCH * G4];   // 256 MiB fp32
__device__ unsigned g_emb_f16[(size_t)VOCAB * D_EMBED / 2];   // packed fp16x2
__device__ unsigned g_wih_f16[(size_t)G4 * D_EMBED / 2];
__device__ unsigned g_h_perm[2][NH / 2];  // ping-pong h, fragment-major fp16
__device__ unsigned g_bar_grp[NGROUP * 32];   // group counters, 128B apart
__device__ unsigned g_bar_root;
__device__ volatile unsigned g_bar_gen;

// ---------------------------------------------------------------------------
// Helpers
// ---------------------------------------------------------------------------
__device__ __forceinline__ unsigned pack_f16x2(float lo, float hi) {
    __half2 h2 = __floats2half2_rn(lo, hi);
    return *(unsigned*)&h2;
}

__device__ __forceinline__ void cpa16(unsigned dst_s, const void* src) {
    asm volatile("cp.async.cg.shared.global [%0], [%1], 16;" :: "r"(dst_s), "l"(src));
}
__device__ __forceinline__ void cpa_commit() {
    asm volatile("cp.async.commit_group;");
}
__device__ __forceinline__ void cpa_wait1() {
    asm volatile("cp.async.wait_group 1;");
}
__device__ __forceinline__ void cpa_wait0() {
    asm volatile("cp.async.wait_group 0;");
}

__device__ __forceinline__ void ldsm_x4(unsigned& r0, unsigned& r1,
                                        unsigned& r2, unsigned& r3, unsigned addr) {
    asm volatile("ldmatrix.sync.aligned.m8n8.x4.shared.b16 {%0,%1,%2,%3}, [%4];"
                 : "=r"(r0), "=r"(r1), "=r"(r2), "=r"(r3) : "r"(addr));
}

// m16n8k16 fp16 MMA, fp32 accumulate
__device__ __forceinline__ void mma_f16(float c[4],
                                        unsigned a0, unsigned a1, unsigned a2, unsigned a3,
                                        unsigned b0, unsigned b1) {
    asm volatile(
        "mma.sync.aligned.m16n8k16.row.col.f32.f16.f16.f32 "
        "{%0,%1,%2,%3}, {%4,%5,%6,%7}, {%8,%9}, {%0,%1,%2,%3};"
        : "+f"(c[0]), "+f"(c[1]), "+f"(c[2]), "+f"(c[3])
        : "r"(a0), "r"(a1), "r"(a2), "r"(a3), "r"(b0), "r"(b1));
}

// Fast sigmoid/tanh via MUFU; abs err ~1e-6, safe vs 1e-3 threshold.
__device__ __forceinline__ float sigf(float x) {
    return __fdividef(1.0f, 1.0f + __expf(-x));
}
__device__ __forceinline__ float tanh_f(float x) {
    return 2.0f * __fdividef(1.0f, 1.0f + __expf(-2.0f * x)) - 1.0f;
}

// ---------------------------------------------------------------------------
// Init: reset barrier state (fresh every launch for graph replay)
// ---------------------------------------------------------------------------
__global__ void init_kernel() {
    int i = threadIdx.x;
    if (i < NGROUP * 32) g_bar_grp[i] = 0;
    if (i == 0) { g_bar_root = 0; g_bar_gen = 0; }
}

// ---------------------------------------------------------------------------
// fp32 -> fp16x2 bulk convert
// ---------------------------------------------------------------------------
__global__ void cvt_f16_kernel(const float4* __restrict__ src,
                               uint2* __restrict__ dst, int n4) {
    int i = blockIdx.x * blockDim.x + threadIdx.x;
    if (i < n4) {
        float4 v = src[i];
        uint2 o;
        o.x = pack_f16x2(v.x, v.y);
        o.y = pack_f16x2(v.z, v.w);
        dst[i] = o;
    }
}

// ---------------------------------------------------------------------------
// Embed gather + input GEMM (fp16 tensor cores, fp32 accum):
// CTA tile 128x128, BK=32 (16 words), 256 threads, warp tile 32x64.
// Operand loads via ldmatrix.x4 (stride-20 rows: conflict-free phases).
// ---------------------------------------------------------------------------
#define EA_STRIDE 20
#define EA_BUF    (128 * EA_STRIDE)      // 2560 words
#define E_B_OFF   (2 * EA_BUF)           // 5120
#define E_TOK_OFF (4 * EA_BUF)           // 10240
#define E_SMEM_WORDS (E_TOK_OFF + 128)   // 10368
#define E_SMEM_BYTES (E_SMEM_WORDS * 4)  // 41472

__global__ __launch_bounds__(256, 2)
void embed_gemm_f16(const int* __restrict__ x_seq,
                    const float* __restrict__ b_ih,
                    const float* __restrict__ b_hh) {
    extern __shared__ unsigned smem[];
    int* tok = (int*)(smem + E_TOK_OFF);

    const int tid  = threadIdx.x;
    const int nblk = blockIdx.x * 128;
    const int mblk = blockIdx.y * 128;

    if (tid < 128) tok[tid] = x_seq[mblk + tid];
    __syncthreads();

    const int w    = tid >> 5;
    const int lane = tid & 31;
    const int g    = lane >> 2;
    const int tig  = lane & 3;
    const int m0   = (w & 3) * 32;
    const int n0   = (w >> 2) * 64;

    const int lrow = tid >> 1;           // 0..127
    const int lc0  = (tid & 1) * 8;      // word offset 0 or 8

    const unsigned sbase = (unsigned)__cvta_generic_to_shared(smem);

    // ldmatrix per-lane address components (byte offsets added to buf base):
    // A matrix j=lane>>3: row = m0 + mi*16 + 8*((lane>>3)&1) + (lane&7),
    //                     word = kw0 + 4*(lane>>4)
    const unsigned a_lane_off =
        (unsigned)(((m0 + 8 * ((lane >> 3) & 1) + (lane & 7)) * EA_STRIDE
                    + 4 * (lane >> 4)) * 4);
    // B matrix j: n-row = n0 + p*16 + 8*(lane>>4) + (lane&7),
    //             word = kw0 + 4*((lane>>3)&1)
    const unsigned b_lane_off =
        (unsigned)(((n0 + 8 * (lane >> 4) + (lane & 7)) * EA_STRIDE
                    + 4 * ((lane >> 3) & 1)) * 4);

    float cfr[2][8][4];
#pragma unroll
    for (int mi = 0; mi < 2; mi++)
#pragma unroll
        for (int ni = 0; ni < 8; ni++)
#pragma unroll
            for (int q = 0; q < 4; q++) cfr[mi][ni][q] = 0.0f;

    const unsigned* asrc_row = g_emb_f16 + (size_t)tok[lrow] * (D_EMBED / 2) + lc0;
    const unsigned* bsrc_row = g_wih_f16 + (size_t)(nblk + lrow) * (D_EMBED / 2) + lc0;

    auto load_chunk = [&](int kc, int buf) {
        unsigned adst = sbase + (buf * EA_BUF + lrow * EA_STRIDE + lc0) * 4;
        const unsigned* asrc = asrc_row + kc * 16;
        cpa16(adst, asrc);
        cpa16(adst + 16, asrc + 4);
        unsigned bdst = sbase + (E_B_OFF + buf * EA_BUF + lrow * EA_STRIDE + lc0) * 4;
        const unsigned* bsrc = bsrc_row + kc * 16;
        cpa16(bdst, bsrc);
        cpa16(bdst + 16, bsrc + 4);
    };

    load_chunk(0, 0);
    cpa_commit();

    for (int kc = 0; kc < 16; kc++) {
        const int buf = kc & 1;
        if (kc + 1 < 16) {
            load_chunk(kc + 1, buf ^ 1);
            cpa_commit();
            cpa_wait1();
        } else {
            cpa_wait0();
        }
        __syncthreads();

        const unsigned Abase = sbase + (unsigned)(buf * EA_BUF) * 4 + a_lane_off;
        const unsigned Bbase = sbase + (unsigned)((E_B_OFF + buf * EA_BUF)) * 4 + b_lane_off;
#pragma unroll
        for (int at = 0; at < 2; at++) {     // 2 k16-atoms per 32-k chunk
            const unsigned kw_b = (unsigned)(at * 8 * 4);   // kw0 bytes
            unsigned afr[2][4];
#pragma unroll
            for (int mi = 0; mi < 2; mi++)
                ldsm_x4(afr[mi][0], afr[mi][1], afr[mi][2], afr[mi][3],
                        Abase + (unsigned)(mi * 16 * EA_STRIDE * 4) + kw_b);
#pragma unroll
            for (int p = 0; p < 4; p++) {    // ni pairs (2p, 2p+1)
                unsigned b0, b1, b2, b3;
                ldsm_x4(b0, b1, b2, b3,
                        Bbase + (unsigned)(p * 16 * EA_STRIDE * 4) + kw_b);
#pragma unroll
                for (int mi = 0; mi < 2; mi++) {
                    mma_f16(cfr[mi][2 * p],     afr[mi][0], afr[mi][1], afr[mi][2], afr[mi][3], b0, b1);
                    mma_f16(cfr[mi][2 * p + 1], afr[mi][0], afr[mi][1], afr[mi][2], afr[mi][3], b2, b3);
                }
            }
        }
        __syncthreads();
    }

#pragma unroll
    for (int ni = 0; ni < 8; ni++) {
        const int col = nblk + n0 + ni * 8 + 2 * tig;
        const float bi0 = b_ih[col] + b_hh[col];
        const float bi1 = b_ih[col + 1] + b_hh[col + 1];
#pragma unroll
        for (int mi = 0; mi < 2; mi++) {
            const int row = mblk + m0 + mi * 16 + g;
            float2 v0 = make_float2(cfr[mi][ni][0] + bi0, cfr[mi][ni][1] + bi1);
            float2 v1 = make_float2(cfr[mi][ni][2] + bi0, cfr[mi][ni][3] + bi1);
            *(float2*)&g_xgates[(size_t)row * G4 + col] = v0;
            *(float2*)&g_xgates[(size_t)(row + 8) * G4 + col] = v1;
        }
    }
}

// ---------------------------------------------------------------------------
// Persistent LSTM recurrence, 128 CTAs x 512 threads (16 warps).
// R9 structure (fp16 m16n8k16, fragment-major layouts, 3-buffer depth-2
// cp.async, 4 gs K-slices) with a TWO-LEVEL monotonic barrier:
// 8 group counters (16 CTAs each, 128B apart) + root counter + gen broadcast.
// ---------------------------------------------------------------------------
#define PTHREADS  512
#define PW_WORDS  16384                   // W permuted: 8 chunks * 2048
#define PA_OFF    PW_WORDS
#define PA_CH     4096                    // words per chunk buffer (64x128 fp16)
#define PGS_OFF   (PA_OFF + 3 * PA_CH)    // 28672
#define GS_SLICE  (64 * 33)               // 2112
#define P_WORDS   (PGS_OFF + 4 * GS_SLICE)   // 37120
#define P_SMEM_BYTES (P_WORDS * 4)           // 148480

__device__ __forceinline__ void grid_barrier(int target, int gr) {
    __syncthreads();
    if (threadIdx.x == 0) {
        __threadfence();
        unsigned old = atomicAdd(&g_bar_grp[gr * 32], 1u);
        if (old == (unsigned)(target * GSIZE - 1)) {
            unsigned r = atomicAdd(&g_bar_root, 1u);
            if (r == (unsigned)(target * NGROUP - 1)) {
                __threadfence();
                g_bar_gen = (unsigned)target;
            }
        }
        while (g_bar_gen < (unsigned)target) { }
        __threadfence();
    }
    __syncthreads();
}

__global__ __launch_bounds__(PTHREADS, 1)
void lstm_persistent(const float* __restrict__ W_hh,
                     float* __restrict__ outs, int out_size) {
    extern __shared__ unsigned smem[];
    unsigned* wp  = smem;
    unsigned* a_s = smem + PA_OFF;
    float*    gs  = (float*)(smem + PGS_OFF);

    const int tid  = threadIdx.x;
    const int bx   = blockIdx.x;
    const int gr   = bx >> 4;
    const int j0   = bx * 8;
    const int w    = tid >> 5;
    const int lane = tid & 31;
    const int g    = lane >> 2;
    const int tig  = lane & 3;
    const int mt   = w & 1;              // batch half: rowblocks mt*2, mt*2+1
    const int nt   = (w >> 1) & 1;       // n half: nb nt*2, nt*2+1
    const int ks   = w >> 2;             // K-split 0..3 (hexes 2ks, 2ks+1)

    // ---- W_hh tile: fp32 -> fp16, permuted fragment-major, resident ----
    {
        unsigned short* wph = (unsigned short*)wp;
        for (int e = tid; e < 32 * D_HIDDEN; e += PTHREADS) {
            const int n = e >> 10;            // local gate-col 0..31
            const int k = e & 1023;
            const int grow = (n >> 3) * D_HIDDEN + j0 + (n & 7);
            const float v = W_hh[(size_t)grow * D_HIDDEN + k];
            const int kcw = k >> 7;
            const int hex = (k >> 4) & 7;
            const unsigned word = kcw * 2048 + hex * 256 + (n >> 3) * 64 +
                                  ((n & 7) * 4 + ((k >> 1) & 3)) * 2 + ((k >> 3) & 1);
            wph[word * 2 + (k & 1)] = __half_as_ushort(__float2half_rn(v));
        }
    }
    __syncthreads();

    // Cell mapping: 1 cell per thread
    const int cb_b = tid >> 3;     // batch 0..63
    const int cu   = tid & 7;      // unit 0..7
    float c_st = 0.0f;

    // Permuted write index (word) for this thread's h value (k=j0+cu, m=cb_b)
    const unsigned hw_word =
        (unsigned)((bx >> 4) * 4096 + ((bx >> 1) & 7) * 512 + (cb_b >> 4) * 128 +
                   ((cb_b & 7) * 4 + (cu >> 1)) * 4 +
                   ((cb_b >> 3) & 1) + 2 * (bx & 1));
    const unsigned hw_half = cu & 1;

    const unsigned sbase = (unsigned)__cvta_generic_to_shared(smem);
    const unsigned adst0 = sbase + (unsigned)(PA_OFF + tid * 8) * 4;

    // x_gates prefetch for t=0
    float xi, xf, xg2, xo;
    {
        const float* p = g_xgates + (size_t)cb_b * G4 + j0 + cu;
        xi  = p[0];
        xf  = p[D_HIDDEN];
        xg2 = p[2 * D_HIDDEN];
        xo  = p[3 * D_HIDDEN];
    }

    for (int t = 0; t < T_STEPS; t++) {
        float cfr[2][2][4];
#pragma unroll
        for (int mi = 0; mi < 2; mi++)
#pragma unroll
            for (int na = 0; na < 2; na++)
#pragma unroll
                for (int q = 0; q < 4; q++) cfr[mi][na][q] = 0.0f;

        if (t > 0) {
            const unsigned* hbase = g_h_perm[(t - 1) & 1] + tid * 8;
            // issue chunks 0, 1 (depth-2)
            cpa16(adst0, hbase);
            cpa16(adst0 + 16, hbase + 4);
            cpa_commit();
            {
                const unsigned d1 = adst0 + (unsigned)PA_CH * 4;
                cpa16(d1, hbase + PA_CH);
                cpa16(d1 + 16, hbase + PA_CH + 4);
                cpa_commit();
            }

#pragma unroll 1
            for (int kc = 0; kc < 8; kc++) {
                if (kc < 7) cpa_wait1(); else cpa_wait0();
                __syncthreads();
                if (kc + 2 < 8) {
                    const unsigned d = adst0 + (unsigned)(((kc + 2) % 3) * PA_CH) * 4;
                    const unsigned* s = hbase + (kc + 2) * PA_CH;
                    cpa16(d, s);
                    cpa16(d + 16, s + 4);
                    cpa_commit();
                }

                const unsigned* A  = a_s + (kc % 3) * PA_CH;
                const unsigned* Wc = wp + kc * 2048;
#pragma unroll
                for (int oi = 0; oi < 2; oi++) {
                    const int hex = ks * 2 + oi;
                    uint4 af[2];
#pragma unroll
                    for (int mi = 0; mi < 2; mi++)
                        af[mi] = *(const uint4*)(A + hex * 512 + (mt * 2 + mi) * 128 + lane * 4);
                    const unsigned* wb = Wc + hex * 256 + lane * 2;
#pragma unroll
                    for (int na = 0; na < 2; na++) {
                        const uint2 bv = *(const uint2*)(wb + (nt * 2 + na) * 64);
                        mma_f16(cfr[0][na], af[0].x, af[0].y, af[0].z, af[0].w, bv.x, bv.y);
                        mma_f16(cfr[1][na], af[1].x, af[1].y, af[1].z, af[1].w, bv.x, bv.y);
                    }
                }
            }
        }

        // Write K-split partials to this group's gs slice
        {
            float* slice = gs + ks * GS_SLICE;
#pragma unroll
            for (int mi = 0; mi < 2; mi++) {
                const int r0 = (mt * 32 + mi * 16 + g) * 33;
#pragma unroll
                for (int na = 0; na < 2; na++) {
                    const int c = nt * 16 + na * 8 + 2 * tig;
                    slice[r0 + c]              = cfr[mi][na][0];
                    slice[r0 + c + 1]          = cfr[mi][na][1];
                    slice[r0 + 8 * 33 + c]     = cfr[mi][na][2];
                    slice[r0 + 8 * 33 + c + 1] = cfr[mi][na][3];
                }
            }
        }
        __syncthreads();

        // Fused elementwise: sum 4 slices + x_gates, activations, cell update
        float s0 = 0.0f, s1 = 0.0f, s2 = 0.0f, s3 = 0.0f;
#pragma unroll
        for (int q = 0; q < 4; q++) {
            const float* gp = gs + q * GS_SLICE + cb_b * 33 + cu;
            s0 += gp[0];
            s1 += gp[8];
            s2 += gp[16];
            s3 += gp[24];
        }
        const float vi = s0 + xi;
        const float vf = s1 + xf;
        const float vg = s2 + xg2;
        const float vo = s3 + xo;

        c_st = sigf(vf) * c_st + sigf(vi) * tanh_f(vg);
        const float hn = sigf(vo) * tanh_f(c_st);

        outs[(size_t)t * NH + (size_t)cb_b * D_HIDDEN + j0 + cu] = hn;
        ((unsigned short*)g_h_perm[t & 1])[hw_word * 2 + hw_half] =
            __half_as_ushort(__float2half_rn(hn));

        if (t == T_STEPS - 1) {
            const size_t base = (size_t)T_STEPS * NH;
            if ((size_t)out_size >= base + 2 * (size_t)NH) {
                const size_t off = (size_t)cb_b * D_HIDDEN + j0 + cu;
                outs[base + off]      = hn;
                outs[base + NH + off] = c_st;
            }
        } else {
            // prefetch x_gates for t+1 (hides DRAM latency behind the barrier)
            const float* p = g_xgates + (size_t)(t + 1) * BATCH * G4
                           + (size_t)cb_b * G4 + j0 + cu;
            xi  = p[0];
            xf  = p[D_HIDDEN];
            xg2 = p[2 * D_HIDDEN];
            xo  = p[3 * D_HIDDEN];
            grid_barrier(t + 1, gr);
        }
    }
}

// ---------------------------------------------------------------------------
extern "C" void kernel_launch(void* const* d_in, const int* in_sizes, int n_in,
                              void* d_out, int out_size)
{
    const int*   x_seq = (const int*)  d_in[0];
    const float* emb   = (const float*)d_in[1];
    const float* W_ih  = (const float*)d_in[2];
    const float* W_hh  = (const float*)d_in[3];
    const float* b_ih  = (const float*)d_in[4];
    const float* b_hh  = (const float*)d_in[5];
    float* out = (float*)d_out;

    cudaFuncSetAttribute(embed_gemm_f16,
                         cudaFuncAttributeMaxDynamicSharedMemorySize, E_SMEM_BYTES);
    cudaFuncSetAttribute(lstm_persistent,
                         cudaFuncAttributeMaxDynamicSharedMemorySize, P_SMEM_BYTES);

    init_kernel<<<1, 256>>>();

    // Pre-convert embedding + W_ih to packed fp16 (W_hh converts inside persistent)
    {
        unsigned* demb; cudaGetSymbolAddress((void**)&demb, g_emb_f16);
        unsigned* dwih; cudaGetSymbolAddress((void**)&dwih, g_wih_f16);
        int n4e = (VOCAB * D_EMBED) / 4;
        int n4i = (G4 * D_EMBED) / 4;
        cvt_f16_kernel<<<(n4e + 255) / 256, 256>>>((const float4*)emb,  (uint2*)demb, n4e);
        cvt_f16_kernel<<<(n4i + 255) / 256, 256>>>((const float4*)W_ih, (uint2*)dwih, n4i);
    }

    dim3 eg(G4 / 128, (T_STEPS * BATCH) / 128);   // (32, 128)
    embed_gemm_f16<<<eg, 256, E_SMEM_BYTES>>>(x_seq, b_ih, b_hh);

    lstm_persistent<<<NCTA, PTHREADS, P_SMEM_BYTES>>>(W_hh, out, out_size);
}

// round 11
// speedup vs baseline: 1.0040x; 1.0040x over previous
#include <cuda_runtime.h>
#include <cuda_fp16.h>
#include <math.h>
#include <stdint.h>

// Problem constants
#define T_STEPS  256
#define BATCH    64
#define VOCAB    32000
#define D_EMBED  512
#define D_HIDDEN 1024
#define G4       (4 * D_HIDDEN)          // 4096
#define NH       (BATCH * D_HIDDEN)      // 65536
#define NCTA     128

// Scratch
__device__ unsigned short g_xgates[(size_t)T_STEPS * BATCH * G4];  // fp16, 128 MiB
__device__ unsigned g_emb_f16[(size_t)VOCAB * D_EMBED / 2];   // packed fp16x2
__device__ unsigned g_wih_f16[(size_t)G4 * D_EMBED / 2];
__device__ unsigned g_h_perm[2][NH / 2];  // ping-pong h, fragment-major fp16
__device__ unsigned g_bar_count;
__device__ volatile unsigned g_bar_gen;

// ---------------------------------------------------------------------------
// Helpers
// ---------------------------------------------------------------------------
__device__ __forceinline__ unsigned pack_f16x2(float lo, float hi) {
    __half2 h2 = __floats2half2_rn(lo, hi);
    return *(unsigned*)&h2;
}

__device__ __forceinline__ void cpa16(unsigned dst_s, const void* src) {
    asm volatile("cp.async.cg.shared.global [%0], [%1], 16;" :: "r"(dst_s), "l"(src));
}
__device__ __forceinline__ void cpa_commit() {
    asm volatile("cp.async.commit_group;");
}
__device__ __forceinline__ void cpa_wait1() {
    asm volatile("cp.async.wait_group 1;");
}
__device__ __forceinline__ void cpa_wait0() {
    asm volatile("cp.async.wait_group 0;");
}

__device__ __forceinline__ void ldsm_x4(unsigned& r0, unsigned& r1,
                                        unsigned& r2, unsigned& r3, unsigned addr) {
    asm volatile("ldmatrix.sync.aligned.m8n8.x4.shared.b16 {%0,%1,%2,%3}, [%4];"
                 : "=r"(r0), "=r"(r1), "=r"(r2), "=r"(r3) : "r"(addr));
}

// m16n8k16 fp16 MMA, fp32 accumulate
__device__ __forceinline__ void mma_f16(float c[4],
                                        unsigned a0, unsigned a1, unsigned a2, unsigned a3,
                                        unsigned b0, unsigned b1) {
    asm volatile(
        "mma.sync.aligned.m16n8k16.row.col.f32.f16.f16.f32 "
        "{%0,%1,%2,%3}, {%4,%5,%6,%7}, {%8,%9}, {%0,%1,%2,%3};"
        : "+f"(c[0]), "+f"(c[1]), "+f"(c[2]), "+f"(c[3])
        : "r"(a0), "r"(a1), "r"(a2), "r"(a3), "r"(b0), "r"(b1));
}

// Fast sigmoid/tanh via MUFU; abs err ~1e-6, safe vs 1e-3 threshold.
__device__ __forceinline__ float sigf(float x) {
    return __fdividef(1.0f, 1.0f + __expf(-x));
}
__device__ __forceinline__ float tanh_f(float x) {
    return 2.0f * __fdividef(1.0f, 1.0f + __expf(-2.0f * x)) - 1.0f;
}

// ---------------------------------------------------------------------------
// Init: reset barrier state (fresh every launch for graph replay)
// ---------------------------------------------------------------------------
__global__ void init_kernel() {
    g_bar_count = 0;
    g_bar_gen = 0;
}

// ---------------------------------------------------------------------------
// fp32 -> fp16x2 bulk convert
// ---------------------------------------------------------------------------
__global__ void cvt_f16_kernel(const float4* __restrict__ src,
                               uint2* __restrict__ dst, int n4) {
    int i = blockIdx.x * blockDim.x + threadIdx.x;
    if (i < n4) {
        float4 v = src[i];
        uint2 o;
        o.x = pack_f16x2(v.x, v.y);
        o.y = pack_f16x2(v.z, v.w);
        dst[i] = o;
    }
}

// ---------------------------------------------------------------------------
// Embed gather + input GEMM (fp16 tensor cores, fp32 accum):
// CTA tile 128x128, BK=32 (16 words), 256 threads, warp tile 32x64.
// Operand loads via ldmatrix.x4; epilogue writes fp16 x_gates (write-bound fix).
// ---------------------------------------------------------------------------
#define EA_STRIDE 20
#define EA_BUF    (128 * EA_STRIDE)      // 2560 words
#define E_B_OFF   (2 * EA_BUF)           // 5120
#define E_TOK_OFF (4 * EA_BUF)           // 10240
#define E_SMEM_WORDS (E_TOK_OFF + 128)   // 10368
#define E_SMEM_BYTES (E_SMEM_WORDS * 4)  // 41472

__global__ __launch_bounds__(256, 2)
void embed_gemm_f16(const int* __restrict__ x_seq,
                    const float* __restrict__ b_ih,
                    const float* __restrict__ b_hh) {
    extern __shared__ unsigned smem[];
    int* tok = (int*)(smem + E_TOK_OFF);

    const int tid  = threadIdx.x;
    const int nblk = blockIdx.x * 128;
    const int mblk = blockIdx.y * 128;

    if (tid < 128) tok[tid] = x_seq[mblk + tid];
    __syncthreads();

    const int w    = tid >> 5;
    const int lane = tid & 31;
    const int g    = lane >> 2;
    const int tig  = lane & 3;
    const int m0   = (w & 3) * 32;
    const int n0   = (w >> 2) * 64;

    const int lrow = tid >> 1;           // 0..127
    const int lc0  = (tid & 1) * 8;      // word offset 0 or 8

    const unsigned sbase = (unsigned)__cvta_generic_to_shared(smem);

    const unsigned a_lane_off =
        (unsigned)(((m0 + 8 * ((lane >> 3) & 1) + (lane & 7)) * EA_STRIDE
                    + 4 * (lane >> 4)) * 4);
    const unsigned b_lane_off =
        (unsigned)(((n0 + 8 * (lane >> 4) + (lane & 7)) * EA_STRIDE
                    + 4 * ((lane >> 3) & 1)) * 4);

    float cfr[2][8][4];
#pragma unroll
    for (int mi = 0; mi < 2; mi++)
#pragma unroll
        for (int ni = 0; ni < 8; ni++)
#pragma unroll
            for (int q = 0; q < 4; q++) cfr[mi][ni][q] = 0.0f;

    const unsigned* asrc_row = g_emb_f16 + (size_t)tok[lrow] * (D_EMBED / 2) + lc0;
    const unsigned* bsrc_row = g_wih_f16 + (size_t)(nblk + lrow) * (D_EMBED / 2) + lc0;

    auto load_chunk = [&](int kc, int buf) {
        unsigned adst = sbase + (buf * EA_BUF + lrow * EA_STRIDE + lc0) * 4;
        const unsigned* asrc = asrc_row + kc * 16;
        cpa16(adst, asrc);
        cpa16(adst + 16, asrc + 4);
        unsigned bdst = sbase + (E_B_OFF + buf * EA_BUF + lrow * EA_STRIDE + lc0) * 4;
        const unsigned* bsrc = bsrc_row + kc * 16;
        cpa16(bdst, bsrc);
        cpa16(bdst + 16, bsrc + 4);
    };

    load_chunk(0, 0);
    cpa_commit();

    for (int kc = 0; kc < 16; kc++) {
        const int buf = kc & 1;
        if (kc + 1 < 16) {
            load_chunk(kc + 1, buf ^ 1);
            cpa_commit();
            cpa_wait1();
        } else {
            cpa_wait0();
        }
        __syncthreads();

        const unsigned Abase = sbase + (unsigned)(buf * EA_BUF) * 4 + a_lane_off;
        const unsigned Bbase = sbase + (unsigned)((E_B_OFF + buf * EA_BUF)) * 4 + b_lane_off;
#pragma unroll
        for (int at = 0; at < 2; at++) {     // 2 k16-atoms per 32-k chunk
            const unsigned kw_b = (unsigned)(at * 8 * 4);
            unsigned afr[2][4];
#pragma unroll
            for (int mi = 0; mi < 2; mi++)
                ldsm_x4(afr[mi][0], afr[mi][1], afr[mi][2], afr[mi][3],
                        Abase + (unsigned)(mi * 16 * EA_STRIDE * 4) + kw_b);
#pragma unroll
            for (int p = 0; p < 4; p++) {    // ni pairs (2p, 2p+1)
                unsigned b0, b1, b2, b3;
                ldsm_x4(b0, b1, b2, b3,
                        Bbase + (unsigned)(p * 16 * EA_STRIDE * 4) + kw_b);
#pragma unroll
                for (int mi = 0; mi < 2; mi++) {
                    mma_f16(cfr[mi][2 * p],     afr[mi][0], afr[mi][1], afr[mi][2], afr[mi][3], b0, b1);
                    mma_f16(cfr[mi][2 * p + 1], afr[mi][0], afr[mi][1], afr[mi][2], afr[mi][3], b2, b3);
                }
            }
        }
        __syncthreads();
    }

    // Epilogue: add bias, write fp16 x_gates (halved write traffic)
#pragma unroll
    for (int ni = 0; ni < 8; ni++) {
        const int col = nblk + n0 + ni * 8 + 2 * tig;   // even
        const float bi0 = b_ih[col] + b_hh[col];
        const float bi1 = b_ih[col + 1] + b_hh[col + 1];
#pragma unroll
        for (int mi = 0; mi < 2; mi++) {
            const int row = mblk + m0 + mi * 16 + g;
            *(unsigned*)&g_xgates[(size_t)row * G4 + col] =
                pack_f16x2(cfr[mi][ni][0] + bi0, cfr[mi][ni][1] + bi1);
            *(unsigned*)&g_xgates[(size_t)(row + 8) * G4 + col] =
                pack_f16x2(cfr[mi][ni][2] + bi0, cfr[mi][ni][3] + bi1);
        }
    }
}

// ---------------------------------------------------------------------------
// Persistent LSTM recurrence, 128 CTAs x 512 threads (16 warps).
// R9 structure exactly (fp16 m16n8k16, fragment-major layouts, 3-buffer
// depth-2 cp.async, 4 gs K-slices, SINGLE-atomic grid barrier), with x_gates
// read as fp16.
// ---------------------------------------------------------------------------
#define PTHREADS  512
#define PW_WORDS  16384                   // W permuted: 8 chunks * 2048
#define PA_OFF    PW_WORDS
#define PA_CH     4096                    // words per chunk buffer (64x128 fp16)
#define PGS_OFF   (PA_OFF + 3 * PA_CH)    // 28672
#define GS_SLICE  (64 * 33)               // 2112
#define P_WORDS   (PGS_OFF + 4 * GS_SLICE)   // 37120
#define P_SMEM_BYTES (P_WORDS * 4)           // 148480

__device__ __forceinline__ void grid_barrier(int target) {
    __syncthreads();
    if (threadIdx.x == 0) {
        __threadfence();
        unsigned old = atomicAdd(&g_bar_count, 1u);
        if (old == NCTA - 1) {
            g_bar_count = 0;
            __threadfence();
            g_bar_gen = (unsigned)target;
        } else {
            while (g_bar_gen < (unsigned)target) { }
        }
        __threadfence();
    }
    __syncthreads();
}

__global__ __launch_bounds__(PTHREADS, 1)
void lstm_persistent(const float* __restrict__ W_hh,
                     float* __restrict__ outs, int out_size) {
    extern __shared__ unsigned smem[];
    unsigned* wp  = smem;
    unsigned* a_s = smem + PA_OFF;
    float*    gs  = (float*)(smem + PGS_OFF);

    const int tid  = threadIdx.x;
    const int bx   = blockIdx.x;
    const int j0   = bx * 8;
    const int w    = tid >> 5;
    const int lane = tid & 31;
    const int g    = lane >> 2;
    const int tig  = lane & 3;
    const int mt   = w & 1;              // batch half: rowblocks mt*2, mt*2+1
    const int nt   = (w >> 1) & 1;       // n half: nb nt*2, nt*2+1
    const int ks   = w >> 2;             // K-split 0..3 (hexes 2ks, 2ks+1)

    // ---- W_hh tile: fp32 -> fp16, permuted fragment-major, resident ----
    {
        unsigned short* wph = (unsigned short*)wp;
        for (int e = tid; e < 32 * D_HIDDEN; e += PTHREADS) {
            const int n = e >> 10;            // local gate-col 0..31
            const int k = e & 1023;
            const int grow = (n >> 3) * D_HIDDEN + j0 + (n & 7);
            const float v = W_hh[(size_t)grow * D_HIDDEN + k];
            const int kcw = k >> 7;
            const int hex = (k >> 4) & 7;
            const unsigned word = kcw * 2048 + hex * 256 + (n >> 3) * 64 +
                                  ((n & 7) * 4 + ((k >> 1) & 3)) * 2 + ((k >> 3) & 1);
            wph[word * 2 + (k & 1)] = __half_as_ushort(__float2half_rn(v));
        }
    }
    __syncthreads();

    // Cell mapping: 1 cell per thread
    const int cb_b = tid >> 3;     // batch 0..63
    const int cu   = tid & 7;      // unit 0..7
    float c_st = 0.0f;

    // Permuted write index (word) for this thread's h value (k=j0+cu, m=cb_b)
    const unsigned hw_word =
        (unsigned)((bx >> 4) * 4096 + ((bx >> 1) & 7) * 512 + (cb_b >> 4) * 128 +
                   ((cb_b & 7) * 4 + (cu >> 1)) * 4 +
                   ((cb_b >> 3) & 1) + 2 * (bx & 1));
    const unsigned hw_half = cu & 1;

    const unsigned sbase = (unsigned)__cvta_generic_to_shared(smem);
    const unsigned adst0 = sbase + (unsigned)(PA_OFF + tid * 8) * 4;

    // x_gates prefetch for t=0 (fp16 scalar loads)
    float xi, xf, xg2, xo;
    {
        const unsigned short* p = g_xgates + (size_t)cb_b * G4 + j0 + cu;
        xi  = __half2float(*(const __half*)(p));
        xf  = __half2float(*(const __half*)(p + D_HIDDEN));
        xg2 = __half2float(*(const __half*)(p + 2 * D_HIDDEN));
        xo  = __half2float(*(const __half*)(p + 3 * D_HIDDEN));
    }

    for (int t = 0; t < T_STEPS; t++) {
        float cfr[2][2][4];
#pragma unroll
        for (int mi = 0; mi < 2; mi++)
#pragma unroll
            for (int na = 0; na < 2; na++)
#pragma unroll
                for (int q = 0; q < 4; q++) cfr[mi][na][q] = 0.0f;

        if (t > 0) {
            const unsigned* hbase = g_h_perm[(t - 1) & 1] + tid * 8;
            // issue chunks 0, 1 (depth-2)
            cpa16(adst0, hbase);
            cpa16(adst0 + 16, hbase + 4);
            cpa_commit();
            {
                const unsigned d1 = adst0 + (unsigned)PA_CH * 4;
                cpa16(d1, hbase + PA_CH);
                cpa16(d1 + 16, hbase + PA_CH + 4);
                cpa_commit();
            }

#pragma unroll 1
            for (int kc = 0; kc < 8; kc++) {
                if (kc < 7) cpa_wait1(); else cpa_wait0();
                __syncthreads();
                if (kc + 2 < 8) {
                    const unsigned d = adst0 + (unsigned)(((kc + 2) % 3) * PA_CH) * 4;
                    const unsigned* s = hbase + (kc + 2) * PA_CH;
                    cpa16(d, s);
                    cpa16(d + 16, s + 4);
                    cpa_commit();
                }

                const unsigned* A  = a_s + (kc % 3) * PA_CH;
                const unsigned* Wc = wp + kc * 2048;
#pragma unroll
                for (int oi = 0; oi < 2; oi++) {
                    const int hex = ks * 2 + oi;
                    uint4 af[2];
#pragma unroll
                    for (int mi = 0; mi < 2; mi++)
                        af[mi] = *(const uint4*)(A + hex * 512 + (mt * 2 + mi) * 128 + lane * 4);
                    const unsigned* wb = Wc + hex * 256 + lane * 2;
#pragma unroll
                    for (int na = 0; na < 2; na++) {
                        const uint2 bv = *(const uint2*)(wb + (nt * 2 + na) * 64);
                        mma_f16(cfr[0][na], af[0].x, af[0].y, af[0].z, af[0].w, bv.x, bv.y);
                        mma_f16(cfr[1][na], af[1].x, af[1].y, af[1].z, af[1].w, bv.x, bv.y);
                    }
                }
            }
        }

        // Write K-split partials to this group's gs slice
        {
            float* slice = gs + ks * GS_SLICE;
#pragma unroll
            for (int mi = 0; mi < 2; mi++) {
                const int r0 = (mt * 32 + mi * 16 + g) * 33;
#pragma unroll
                for (int na = 0; na < 2; na++) {
                    const int c = nt * 16 + na * 8 + 2 * tig;
                    slice[r0 + c]              = cfr[mi][na][0];
                    slice[r0 + c + 1]          = cfr[mi][na][1];
                    slice[r0 + 8 * 33 + c]     = cfr[mi][na][2];
                    slice[r0 + 8 * 33 + c + 1] = cfr[mi][na][3];
                }
            }
        }
        __syncthreads();

        // Fused elementwise: sum 4 slices + x_gates, activations, cell update
        float s0 = 0.0f, s1 = 0.0f, s2 = 0.0f, s3 = 0.0f;
#pragma unroll
        for (int q = 0; q < 4; q++) {
            const float* gp = gs + q * GS_SLICE + cb_b * 33 + cu;
            s0 += gp[0];
            s1 += gp[8];
            s2 += gp[16];
            s3 += gp[24];
        }
        const float vi = s0 + xi;
        const float vf = s1 + xf;
        const float vg = s2 + xg2;
        const float vo = s3 + xo;

        c_st = sigf(vf) * c_st + sigf(vi) * tanh_f(vg);
        const float hn = sigf(vo) * tanh_f(c_st);

        outs[(size_t)t * NH + (size_t)cb_b * D_HIDDEN + j0 + cu] = hn;
        ((unsigned short*)g_h_perm[t & 1])[hw_word * 2 + hw_half] =
            __half_as_ushort(__float2half_rn(hn));

        if (t == T_STEPS - 1) {
            const size_t base = (size_t)T_STEPS * NH;
            if ((size_t)out_size >= base + 2 * (size_t)NH) {
                const size_t off = (size_t)cb_b * D_HIDDEN + j0 + cu;
                outs[base + off]      = hn;
                outs[base + NH + off] = c_st;
            }
        } else {
            // prefetch x_gates for t+1 (hides latency behind the barrier)
            const unsigned short* p = g_xgates + (size_t)(t + 1) * BATCH * G4
                                    + (size_t)cb_b * G4 + j0 + cu;
            xi  = __half2float(*(const __half*)(p));
            xf  = __half2float(*(const __half*)(p + D_HIDDEN));
            xg2 = __half2float(*(const __half*)(p + 2 * D_HIDDEN));
            xo  = __half2float(*(const __half*)(p + 3 * D_HIDDEN));
            grid_barrier(t + 1);
        }
    }
}

// ---------------------------------------------------------------------------
extern "C" void kernel_launch(void* const* d_in, const int* in_sizes, int n_in,
                              void* d_out, int out_size)
{
    const int*   x_seq = (const int*)  d_in[0];
    const float* emb   = (const float*)d_in[1];
    const float* W_ih  = (const float*)d_in[2];
    const float* W_hh  = (const float*)d_in[3];
    const float* b_ih  = (const float*)d_in[4];
    const float* b_hh  = (const float*)d_in[5];
    float* out = (float*)d_out;

    cudaFuncSetAttribute(embed_gemm_f16,
                         cudaFuncAttributeMaxDynamicSharedMemorySize, E_SMEM_BYTES);
    cudaFuncSetAttribute(lstm_persistent,
                         cudaFuncAttributeMaxDynamicSharedMemorySize, P_SMEM_BYTES);

    init_kernel<<<1, 1>>>();

    // Pre-convert embedding + W_ih to packed fp16 (W_hh converts inside persistent)
    {
        unsigned* demb; cudaGetSymbolAddress((void**)&demb, g_emb_f16);
        unsigned* dwih; cudaGetSymbolAddress((void**)&dwih, g_wih_f16);
        int n4e = (VOCAB * D_EMBED) / 4;
        int n4i = (G4 * D_EMBED) / 4;
        cvt_f16_kernel<<<(n4e + 255) / 256, 256>>>((const float4*)emb,  (uint2*)demb, n4e);
        cvt_f16_kernel<<<(n4i + 255) / 256, 256>>>((const float4*)W_ih, (uint2*)dwih, n4i);
    }

    dim3 eg(G4 / 128, (T_STEPS * BATCH) / 128);   // (32, 128)
    embed_gemm_f16<<<eg, 256, E_SMEM_BYTES>>>(x_seq, b_ih, b_hh);

    lstm_persistent<<<NCTA, PTHREADS, P_SMEM_BYTES>>>(W_hh, out, out_size);
}